// round 5
// baseline (speedup 1.0000x reference)
#include <cuda_runtime.h>
#include <cuda_fp16.h>

#define NN 50000
#define EE 800000
#define EP (EE + NN)
#define HH 4
#define CC 32
#define HC 128
#define EDIM 8
#define NRELS 16
#define NLAYERS 3
#define HID 100

typedef unsigned long long ull;

// ---------- scratch (device globals: no allocation allowed) ----------
__device__ __half g_hh[NN * HC];        // projected features (fp16, message table)
__device__ float g_xA[NN * HC];         // ping
__device__ float g_xB[NN * HC];         // pong
__device__ float g_ssrc[NN * HH];
__device__ float g_sdst[NN * HH];
__device__ int   g_rowstart[NN + 1];
__device__ int   g_counts[NN];
__device__ int   g_cursor[NN];
__device__ unsigned g_edgep[EP];        // src | (type<<16), sorted by dst
__device__ float g_serel[NLAYERS * (NRELS + 1) * HH];
__device__ float g_w0sum[HC];
__device__ float g_k0[8];               // layer0 rank-1 att dots (src 0..3, dst 4..7)
__device__ int   g_hist[NRELS];

// ---------- f32x2 helpers ----------
__device__ __forceinline__ void ffma2(ull &d, ull a, ull b) {
    asm("fma.rn.f32x2 %0, %1, %2, %3;" : "=l"(d) : "l"(a), "l"(b), "l"(d));
}
__device__ __forceinline__ ull pack2(float x, float y) {
    ull r; asm("mov.b64 %0, {%1, %2};" : "=l"(r) : "f"(x), "f"(y)); return r;
}
__device__ __forceinline__ float lo2(ull v) { return __uint_as_float((unsigned)v); }
__device__ __forceinline__ float hi2(ull v) { return __uint_as_float((unsigned)(v >> 32)); }

#define NEGINF __int_as_float(0xff800000)

// ---------- build: counts + type histogram ----------
__global__ void k_init() {
    int i = blockIdx.x * blockDim.x + threadIdx.x;
    if (i < NN) g_counts[i] = 1;          // self-loop
    if (i < NRELS) g_hist[i] = 0;
}

__global__ void k_histcount(const int* __restrict__ ei, const int* __restrict__ et) {
    __shared__ int sh[NRELS];
    if (threadIdx.x < NRELS) sh[threadIdx.x] = 0;
    __syncthreads();
    int i = blockIdx.x * blockDim.x + threadIdx.x;
    if (i < EE) {
        atomicAdd(&g_counts[ei[EE + i]], 1);
        atomicAdd(&sh[et[i]], 1);
    }
    __syncthreads();
    if (threadIdx.x < NRELS) atomicAdd(&g_hist[threadIdx.x], sh[threadIdx.x]);
}

// ---------- exclusive scan (1 block, hierarchical) ----------
__global__ void k_scan() {
    __shared__ int ss[1024];
    const int CH = (NN + 1023) / 1024;
    int t = threadIdx.x;
    int beg = t * CH;
    int end = min(beg + CH, NN);
    int s = 0;
    for (int i = beg; i < end; i++) s += g_counts[i];
    ss[t] = s;
    __syncthreads();
    for (int off = 1; off < 1024; off <<= 1) {
        int v = 0;
        if (t >= off) v = ss[t - off];
        __syncthreads();
        ss[t] += v;
        __syncthreads();
    }
    int run = (t == 0) ? 0 : ss[t - 1];
    for (int i = beg; i < end; i++) {
        g_rowstart[i] = run;
        g_cursor[i]   = run;
        run += g_counts[i];
    }
    if (t == 0) g_rowstart[NN] = EP;
}

// ---------- scatter edges into dst-CSR (packed: src | type<<16) ----------
__global__ void k_scatter(const int* __restrict__ ei, const int* __restrict__ et) {
    int i = blockIdx.x * blockDim.x + threadIdx.x;
    if (i < EE) {
        int d = ei[EE + i];
        int p = atomicAdd(&g_cursor[d], 1);
        g_edgep[p] = (unsigned)ei[i] | ((unsigned)et[i] << 16);
    } else if (i < EP) {
        int n = i - EE;
        int p = atomicAdd(&g_cursor[n], 1);
        g_edgep[p] = (unsigned)n | ((unsigned)NRELS << 16);   // self-loop sentinel
    }
}

// ---------- tiny precompute ----------
__global__ void k_pre(const float* __restrict__ W0, const float* __restrict__ Wedge,
                      const float* __restrict__ attE, const float* __restrict__ eemb,
                      const float* __restrict__ attS, const float* __restrict__ attD) {
    int t = threadIdx.x;
    if (t < HC) {
        float s = 0.f;
        for (int c = 0; c < CC; c++) s += W0[c * HC + t];
        g_w0sum[t] = s;
    }
    if (t < NLAYERS * (NRELS + 1) * HH) {
        int l = t / ((NRELS + 1) * HH);
        int rem = t % ((NRELS + 1) * HH);
        int r = rem / HH;
        int h = rem % HH;
        float s = 0.f;
        for (int d = 0; d < EDIM; d++) {
            float u = 0.f;
            for (int c = 0; c < CC; c++)
                u += Wedge[(l * EDIM + d) * HC + h * CC + c] * attE[l * HC + h * CC + c];
            float ea;
            if (r < NRELS) {
                ea = eemb[r * EDIM + d];
            } else {
                float f = 0.f;
                for (int rr = 0; rr < NRELS; rr++)
                    f += (float)g_hist[rr] * eemb[rr * EDIM + d];
                ea = f / (float)EE;
            }
            s += ea * u;
        }
        g_serel[t] = s;
    }
    __syncthreads();
    if (t < 8) {                    // layer-0 rank-1 attention dots
        int h = t & 3;
        const float* av = (t < 4) ? attS : attD;
        float s = 0.f;
        for (int c = 0; c < CC; c++) s += g_w0sum[h * CC + c] * av[h * CC + c];
        g_k0[t] = s;
    }
}

// ---------- layer-0 aggregation: rank-1, 4-stream scalar online softmax ----------
__global__ void __launch_bounds__(256) k_agg0(const float* __restrict__ x,
                                              const float* __restrict__ bias,
                                              float* __restrict__ xout) {
    __shared__ float sser[(NRELS + 1) * HH];
    int t = threadIdx.x;
    if (t < (NRELS + 1) * HH) sser[t] = g_serel[t];
    __syncthreads();
    int warp = t >> 5, lane = t & 31;
    int n = blockIdx.x * 8 + warp;
    if (n >= NN) return;
    int hd = lane >> 3;
    float4 w4 = ((const float4*)g_w0sum)[lane];
    float k0s = g_k0[hd];
    int beg = g_rowstart[n], end = g_rowstart[n + 1];
    float sdv = x[n] * g_k0[4 + hd];

    float m[4], ds[4], sx[4];
#pragma unroll
    for (int i = 0; i < 4; i++) { m[i] = -1e30f; ds[i] = 0.f; sx[i] = 0.f; }

    for (int base = beg; base < end; base += 32) {
        int rem = end - base; if (rem > 32) rem = 32;
        unsigned pkv = g_edgep[base + (lane < rem ? lane : 0)];
        int nb = (rem + 3) >> 2;
        float xsA[4], ofA[4], xsB[4], ofB[4];

        auto ld = [&](int b, float* xs, float* of) {
#pragma unroll
            for (int i = 0; i < 4; i++) {
                int j = (b << 2) + i;
                unsigned p = __shfl_sync(0xffffffffu, pkv, j < rem ? j : 0);
                xs[i] = (j < rem) ? x[p & 0xFFFFu] : 0.f;
                of[i] = (j < rem) ? (sdv + sser[(p >> 16) * HH + hd]) : NEGINF;
            }
        };
        auto pr = [&](const float* xs, const float* of) {
#pragma unroll
            for (int i = 0; i < 4; i++) {
                float a = xs[i] * k0s + of[i];
                a = (a > 0.f) ? a : 0.2f * a;
                float nm = fmaxf(m[i], a);
                float sc = __expf(m[i] - nm);
                float w  = __expf(a - nm);
                m[i] = nm;
                ds[i] = ds[i] * sc + w;
                sx[i] = sx[i] * sc + w * xs[i];
            }
        };
        ld(0, xsA, ofA);
        for (int b = 0; b < nb; b += 2) {
            if (b + 1 < nb) ld(b + 1, xsB, ofB);
            pr(xsA, ofA);
            if (b + 1 >= nb) break;
            if (b + 2 < nb) ld(b + 2, xsA, ofA);
            pr(xsB, ofB);
        }
    }
    float M = fmaxf(fmaxf(m[0], m[1]), fmaxf(m[2], m[3]));
    float dsum = 0.f, sxt = 0.f;
#pragma unroll
    for (int i = 0; i < 4; i++) {
        float w = __expf(m[i] - M);
        dsum += w * ds[i];
        sxt  += w * sx[i];
    }
    float s = sxt / (dsum + 1e-16f);
    float4 b4 = ((const float4*)bias)[lane];
    float4 o = make_float4(fmaxf(s * w4.x + b4.x, 0.f), fmaxf(s * w4.y + b4.y, 0.f),
                           fmaxf(s * w4.z + b4.z, 0.f), fmaxf(s * w4.w + b4.w, 0.f));
    ((float4*)xout)[n * 32 + lane] = o;
}

// ---------- layers 1,2 aggregation: cooperative pack load + 4 streams + pipeline ----------
__global__ void __launch_bounds__(256) k_agg(const float* __restrict__ bias,
                                             const float* __restrict__ xprev,
                                             float* __restrict__ xout, int layer) {
    __shared__ float sser[(NRELS + 1) * HH];
    int t = threadIdx.x;
    if (t < (NRELS + 1) * HH) sser[t] = g_serel[layer * (NRELS + 1) * HH + t];
    __syncthreads();
    int warp = t >> 5, lane = t & 31;
    int n = blockIdx.x * 8 + warp;
    if (n >= NN) return;
    int hd = lane >> 3;
    int beg = g_rowstart[n], end = g_rowstart[n + 1];
    float sdv = g_sdst[n * HH + hd];

    float m[4], ds[4];
    float4 acc[4];
#pragma unroll
    for (int i = 0; i < 4; i++) {
        m[i] = -1e30f; ds[i] = 0.f;
        acc[i] = make_float4(0.f, 0.f, 0.f, 0.f);
    }

    for (int base = beg; base < end; base += 32) {
        int rem = end - base; if (rem > 32) rem = 32;
        unsigned pkv = g_edgep[base + (lane < rem ? lane : 0)];
        int nb = (rem + 3) >> 2;
        float ssA[4], ssB[4];
        uint2 rvA[4], rvB[4];
        int tyA[4], tyB[4];

        auto ld = [&](int b, float* ss, uint2* rv, int* ty) {
#pragma unroll
            for (int i = 0; i < 4; i++) {
                int j = (b << 2) + i;
                unsigned p = __shfl_sync(0xffffffffu, pkv, j < rem ? j : 0);
                int src = (int)(p & 0xFFFFu);
                ty[i] = (int)(p >> 16);
                ss[i] = (j < rem) ? g_ssrc[src * HH + hd] : NEGINF;
                rv[i] = ((const uint2*)(g_hh + src * HC))[lane];
            }
        };
        auto pr = [&](const float* ss, const uint2* rv, const int* ty) {
#pragma unroll
            for (int i = 0; i < 4; i++) {
                float a = ss[i] + sdv + sser[ty[i] * HH + hd];
                a = (a > 0.f) ? a : 0.2f * a;
                float nm = fmaxf(m[i], a);
                float sc = __expf(m[i] - nm);
                float w  = __expf(a - nm);
                m[i] = nm;
                float2 f0 = __half22float2(*(const __half2*)&rv[i].x);
                float2 f1 = __half22float2(*(const __half2*)&rv[i].y);
                ds[i] = ds[i] * sc + w;
                acc[i].x = acc[i].x * sc + w * f0.x;
                acc[i].y = acc[i].y * sc + w * f0.y;
                acc[i].z = acc[i].z * sc + w * f1.x;
                acc[i].w = acc[i].w * sc + w * f1.y;
            }
        };
        ld(0, ssA, rvA, tyA);
        for (int b = 0; b < nb; b += 2) {
            if (b + 1 < nb) ld(b + 1, ssB, rvB, tyB);
            pr(ssA, rvA, tyA);
            if (b + 1 >= nb) break;
            if (b + 2 < nb) ld(b + 2, ssA, rvA, tyA);
            pr(ssB, rvB, tyB);
        }
    }
    // merge 4 streams
    float M = fmaxf(fmaxf(m[0], m[1]), fmaxf(m[2], m[3]));
    float dsum = 0.f;
    float4 A4 = make_float4(0.f, 0.f, 0.f, 0.f);
#pragma unroll
    for (int i = 0; i < 4; i++) {
        float w = __expf(m[i] - M);
        dsum += w * ds[i];
        A4.x += w * acc[i].x; A4.y += w * acc[i].y;
        A4.z += w * acc[i].z; A4.w += w * acc[i].w;
    }
    float inv = 1.f / (dsum + 1e-16f);
    float4 b4 = ((const float4*)bias)[lane];
    float4 xp = ((const float4*)xprev)[n * 32 + lane];
    float4 o = make_float4(A4.x * inv + b4.x + xp.x, A4.y * inv + b4.y + xp.y,
                           A4.z * inv + b4.z + xp.z, A4.w * inv + b4.w + xp.w);
    o.x = fmaxf(o.x, 0.f); o.y = fmaxf(o.y, 0.f);
    o.z = fmaxf(o.z, 0.f); o.w = fmaxf(o.w, 0.f);
    ((float4*)xout)[n * 32 + lane] = o;
}

// ---------- f32x2 SGEMM + fused epilogue: h(fp16), s_src, s_dst ----------
__global__ void __launch_bounds__(256) k_gemm(const float* __restrict__ A,
                                              const float* __restrict__ B,
                                              const float* __restrict__ attS,
                                              const float* __restrict__ attD,
                                              int M) {
    __shared__ float As[16][HC];
    __shared__ float Bs[16][HC];
    __shared__ float sa[HC], sd[HC];
    int t = threadIdx.x;
    int tx = t & 15, ty = t >> 4;
    int row0 = blockIdx.x * 128;
    if (t < HC) { sa[t] = attS[t]; sd[t] = attD[t]; }
    ull acc2[8][4];
#pragma unroll
    for (int i = 0; i < 8; i++)
#pragma unroll
        for (int j = 0; j < 4; j++) acc2[i][j] = 0ull;

    for (int kc = 0; kc < 128; kc += 16) {
#pragma unroll
        for (int i = 0; i < 2; i++) {
            int f = t * 2 + i;
            int r = f >> 2;
            int kq = (f & 3) << 2;
            float4 v = make_float4(0, 0, 0, 0);
            int gr = row0 + r;
            if (gr < M) v = *(const float4*)(A + gr * 128 + kc + kq);
            As[kq + 0][r] = v.x; As[kq + 1][r] = v.y;
            As[kq + 2][r] = v.z; As[kq + 3][r] = v.w;
        }
#pragma unroll
        for (int i = 0; i < 2; i++) {
            int f = t * 2 + i;
            int k = f >> 5;
            int cq = (f & 31) << 2;
            float4 v = *(const float4*)(B + (kc + k) * 128 + cq);
            Bs[k][cq + 0] = v.x; Bs[k][cq + 1] = v.y;
            Bs[k][cq + 2] = v.z; Bs[k][cq + 3] = v.w;
        }
        __syncthreads();
#pragma unroll
        for (int k = 0; k < 16; k++) {
            float4 a0 = *(const float4*)&As[k][ty * 8];
            float4 a1 = *(const float4*)&As[k][ty * 8 + 4];
            float4 b0 = *(const float4*)&Bs[k][tx * 8];
            float4 b1 = *(const float4*)&Bs[k][tx * 8 + 4];
            ull bb[4] = { pack2(b0.x, b0.y), pack2(b0.z, b0.w),
                          pack2(b1.x, b1.y), pack2(b1.z, b1.w) };
            float avs[8] = { a0.x, a0.y, a0.z, a0.w, a1.x, a1.y, a1.z, a1.w };
#pragma unroll
            for (int i = 0; i < 8; i++) {
                ull aa = pack2(avs[i], avs[i]);
#pragma unroll
                for (int j = 0; j < 4; j++) ffma2(acc2[i][j], aa, bb[j]);
            }
        }
        __syncthreads();
    }
    // epilogue: fp16 h store + fused s_src/s_dst (quad-shuffle over tx%4)
    int hd = tx >> 2;
#pragma unroll
    for (int i = 0; i < 8; i++) {
        int gr = row0 + ty * 8 + i;
        float f[8];
#pragma unroll
        for (int j = 0; j < 4; j++) { f[2 * j] = lo2(acc2[i][j]); f[2 * j + 1] = hi2(acc2[i][j]); }
        float ps = 0.f, pd = 0.f;
#pragma unroll
        for (int j = 0; j < 8; j++) {
            ps += f[j] * sa[tx * 8 + j];
            pd += f[j] * sd[tx * 8 + j];
        }
        ps += __shfl_xor_sync(0xffffffffu, ps, 1);
        pd += __shfl_xor_sync(0xffffffffu, pd, 1);
        ps += __shfl_xor_sync(0xffffffffu, ps, 2);
        pd += __shfl_xor_sync(0xffffffffu, pd, 2);
        if (gr < M) {
            __half2 h0 = __floats2half2_rn(f[0], f[1]);
            __half2 h1 = __floats2half2_rn(f[2], f[3]);
            __half2 h2 = __floats2half2_rn(f[4], f[5]);
            __half2 h3 = __floats2half2_rn(f[6], f[7]);
            uint4 u = make_uint4(*(unsigned*)&h0, *(unsigned*)&h1,
                                 *(unsigned*)&h2, *(unsigned*)&h3);
            *(uint4*)(g_hh + gr * HC + tx * 8) = u;
            if ((tx & 3) == 0) {
                g_ssrc[gr * HH + hd] = ps;
                g_sdst[gr * HH + hd] = pd;
            }
        }
    }
}

// ---------- fused MLP head: out = sigmoid(relu(A@W1+b1)@W2 + b2) ----------
__global__ void __launch_bounds__(256) k_mlp(const float* __restrict__ A,
                                             const float* __restrict__ W1,
                                             const float* __restrict__ b1,
                                             const float* __restrict__ W2,
                                             const float* __restrict__ b2,
                                             float* __restrict__ out, int M) {
    __shared__ float As[16][HC];
    __shared__ float Bs[16][HC];
    __shared__ float sred[128][17];
    __shared__ float sw2[HC];
    __shared__ float sb1[HC];
    int t = threadIdx.x;
    int tx = t & 15, ty = t >> 4;
    int row0 = blockIdx.x * 128;
    if (t < HC) {
        sw2[t] = (t < HID) ? W2[t] : 0.f;
        sb1[t] = (t < HID) ? b1[t] : 0.f;
    }
    ull acc2[8][4];
#pragma unroll
    for (int i = 0; i < 8; i++)
#pragma unroll
        for (int j = 0; j < 4; j++) acc2[i][j] = 0ull;

    for (int kc = 0; kc < 128; kc += 16) {
#pragma unroll
        for (int i = 0; i < 2; i++) {
            int f = t * 2 + i;
            int r = f >> 2;
            int kq = (f & 3) << 2;
            float4 v = make_float4(0, 0, 0, 0);
            int gr = row0 + r;
            if (gr < M) v = *(const float4*)(A + gr * 128 + kc + kq);
            As[kq + 0][r] = v.x; As[kq + 1][r] = v.y;
            As[kq + 2][r] = v.z; As[kq + 3][r] = v.w;
        }
#pragma unroll
        for (int i = 0; i < 2; i++) {
            int f = t * 2 + i;
            int k = f >> 5;
            int cq = (f & 31) << 2;
            float4 v = make_float4(0, 0, 0, 0);
            if (cq < HID) v = *(const float4*)(W1 + (kc + k) * HID + cq);
            Bs[k][cq + 0] = v.x; Bs[k][cq + 1] = v.y;
            Bs[k][cq + 2] = v.z; Bs[k][cq + 3] = v.w;
        }
        __syncthreads();
#pragma unroll
        for (int k = 0; k < 16; k++) {
            float4 a0 = *(const float4*)&As[k][ty * 8];
            float4 a1 = *(const float4*)&As[k][ty * 8 + 4];
            float4 b0 = *(const float4*)&Bs[k][tx * 8];
            float4 b1v = *(const float4*)&Bs[k][tx * 8 + 4];
            ull bb[4] = { pack2(b0.x, b0.y), pack2(b0.z, b0.w),
                          pack2(b1v.x, b1v.y), pack2(b1v.z, b1v.w) };
            float avs[8] = { a0.x, a0.y, a0.z, a0.w, a1.x, a1.y, a1.z, a1.w };
#pragma unroll
            for (int i = 0; i < 8; i++) {
                ull aa = pack2(avs[i], avs[i]);
#pragma unroll
                for (int j = 0; j < 4; j++) ffma2(acc2[i][j], aa, bb[j]);
            }
        }
        __syncthreads();
    }
#pragma unroll
    for (int i = 0; i < 8; i++) {
        float p = 0.f;
#pragma unroll
        for (int j = 0; j < 4; j++) {
            int gc = tx * 8 + 2 * j;
            float v0 = fmaxf(lo2(acc2[i][j]) + sb1[gc], 0.f);
            float v1 = fmaxf(hi2(acc2[i][j]) + sb1[gc + 1], 0.f);
            p += v0 * sw2[gc] + v1 * sw2[gc + 1];
        }
        sred[ty * 8 + i][tx] = p;
    }
    __syncthreads();
    if (t < 128) {
        int gr = row0 + t;
        if (gr < M) {
            float s = 0.f;
#pragma unroll
            for (int j = 0; j < 16; j++) s += sred[t][j];
            out[gr] = 1.f / (1.f + __expf(-(s + b2[0])));
        }
    }
}

// ---------- host ----------
extern "C" void kernel_launch(void* const* d_in, const int* in_sizes, int n_in,
                              void* d_out, int out_size) {
    const float* x     = (const float*)d_in[0];
    const int*   ei    = (const int*)d_in[1];
    const int*   et    = (const int*)d_in[2];
    const float* eemb  = (const float*)d_in[3];
    const float* W0    = (const float*)d_in[4];
    const float* W1    = (const float*)d_in[5];
    const float* W2    = (const float*)d_in[6];
    const float* attS  = (const float*)d_in[7];
    const float* attD  = (const float*)d_in[8];
    const float* attE  = (const float*)d_in[9];
    const float* Wedge = (const float*)d_in[10];
    const float* bias  = (const float*)d_in[11];
    const float* mW1   = (const float*)d_in[12];
    const float* mb1   = (const float*)d_in[13];
    const float* mW2   = (const float*)d_in[14];
    const float* mb2   = (const float*)d_in[15];
    float* out = (float*)d_out;

    float *pxA, *pxB;
    cudaGetSymbolAddress((void**)&pxA, g_xA);
    cudaGetSymbolAddress((void**)&pxB, g_xB);

    // graph build (reused by all 3 layers)
    k_init<<<(NN + 255) / 256, 256>>>();
    k_histcount<<<(EE + 255) / 256, 256>>>(ei, et);
    k_scan<<<1, 1024>>>();
    k_scatter<<<(EP + 255) / 256, 256>>>(ei, et);
    k_pre<<<1, 256>>>(W0, Wedge, attE, eemb, attS, attD);

    int gAgg = (NN + 7) / 8;
    int gGm  = (NN + 127) / 128;

    // layer 0: fully rank-1 aggregation (no h materialization at all)
    k_agg0<<<gAgg, 256>>>(x, bias + 0 * HC, pxA);

    // layer 1
    k_gemm<<<gGm, 256>>>(pxA, W1, attS + 1 * HC, attD + 1 * HC, NN);
    k_agg<<<gAgg, 256>>>(bias + 1 * HC, pxA, pxB, 1);

    // layer 2
    k_gemm<<<gGm, 256>>>(pxB, W2, attS + 2 * HC, attD + 2 * HC, NN);
    k_agg<<<gAgg, 256>>>(bias + 2 * HC, pxB, pxA, 2);

    // fused MLP head
    k_mlp<<<gGm, 256>>>(pxA, mW1, mb1, mW2, mb2, out, NN);
}

// round 6
// speedup vs baseline: 1.2207x; 1.2207x over previous
#include <cuda_runtime.h>
#include <cuda_fp16.h>

#define NN 50000
#define EE 800000
#define EP (EE + NN)
#define HH 4
#define CC 32
#define HC 128
#define EDIM 8
#define NRELS 16
#define NLAYERS 3
#define HID 100

typedef unsigned long long ull;

// ---------- scratch (device globals: no allocation allowed) ----------
__device__ __half g_hh[NN * HC];        // projected features (fp16, message table)
__device__ float g_xA[NN * HC];         // ping
__device__ float g_xB[NN * HC];         // pong
__device__ float g_ssrc[NN * HH];
__device__ float g_sdst[NN * HH];
__device__ int   g_rowstart[NN + 1];
__device__ int   g_counts[NN];
__device__ int   g_cursor[NN];
__device__ unsigned g_edgep[EP];        // src | (type<<16), sorted by dst
__device__ float g_serel[NLAYERS * (NRELS + 1) * HH];
__device__ float g_w0sum[HC];
__device__ float g_k0[8];               // layer0 rank-1 att dots (src 0..3, dst 4..7)
__device__ int   g_hist[NRELS];

// ---------- f32x2 helpers ----------
__device__ __forceinline__ void ffma2(ull &d, ull a, ull b) {
    asm("fma.rn.f32x2 %0, %1, %2, %3;" : "=l"(d) : "l"(a), "l"(b), "l"(d));
}
__device__ __forceinline__ ull pack2(float x, float y) {
    ull r; asm("mov.b64 %0, {%1, %2};" : "=l"(r) : "f"(x), "f"(y)); return r;
}
__device__ __forceinline__ float lo2(ull v) { return __uint_as_float((unsigned)v); }
__device__ __forceinline__ float hi2(ull v) { return __uint_as_float((unsigned)(v >> 32)); }

// ---------- build: counts + type histogram ----------
__global__ void k_init() {
    int i = blockIdx.x * blockDim.x + threadIdx.x;
    if (i < NN) g_counts[i] = 1;          // self-loop
    if (i < NRELS) g_hist[i] = 0;
}

__global__ void k_histcount(const int* __restrict__ ei, const int* __restrict__ et) {
    __shared__ int sh[NRELS];
    if (threadIdx.x < NRELS) sh[threadIdx.x] = 0;
    __syncthreads();
    int i = blockIdx.x * blockDim.x + threadIdx.x;
    if (i < EE) {
        atomicAdd(&g_counts[ei[EE + i]], 1);
        atomicAdd(&sh[et[i]], 1);
    }
    __syncthreads();
    if (threadIdx.x < NRELS) atomicAdd(&g_hist[threadIdx.x], sh[threadIdx.x]);
}

// ---------- exclusive scan (1 block, hierarchical) ----------
__global__ void k_scan() {
    __shared__ int ss[1024];
    const int CH = (NN + 1023) / 1024;
    int t = threadIdx.x;
    int beg = t * CH;
    int end = min(beg + CH, NN);
    int s = 0;
    for (int i = beg; i < end; i++) s += g_counts[i];
    ss[t] = s;
    __syncthreads();
    for (int off = 1; off < 1024; off <<= 1) {
        int v = 0;
        if (t >= off) v = ss[t - off];
        __syncthreads();
        ss[t] += v;
        __syncthreads();
    }
    int run = (t == 0) ? 0 : ss[t - 1];
    for (int i = beg; i < end; i++) {
        g_rowstart[i] = run;
        g_cursor[i]   = run;
        run += g_counts[i];
    }
    if (t == 0) g_rowstart[NN] = EP;
}

// ---------- scatter edges into dst-CSR (packed: src | type<<16) ----------
__global__ void k_scatter(const int* __restrict__ ei, const int* __restrict__ et) {
    int i = blockIdx.x * blockDim.x + threadIdx.x;
    if (i < EE) {
        int d = ei[EE + i];
        int p = atomicAdd(&g_cursor[d], 1);
        g_edgep[p] = (unsigned)ei[i] | ((unsigned)et[i] << 16);
    } else if (i < EP) {
        int n = i - EE;
        int p = atomicAdd(&g_cursor[n], 1);
        g_edgep[p] = (unsigned)n | ((unsigned)NRELS << 16);   // self-loop sentinel
    }
}

// ---------- tiny precompute ----------
__global__ void k_pre(const float* __restrict__ W0, const float* __restrict__ Wedge,
                      const float* __restrict__ attE, const float* __restrict__ eemb,
                      const float* __restrict__ attS, const float* __restrict__ attD) {
    int t = threadIdx.x;
    if (t < HC) {
        float s = 0.f;
        for (int c = 0; c < CC; c++) s += W0[c * HC + t];
        g_w0sum[t] = s;
    }
    if (t < NLAYERS * (NRELS + 1) * HH) {
        int l = t / ((NRELS + 1) * HH);
        int rem = t % ((NRELS + 1) * HH);
        int r = rem / HH;
        int h = rem % HH;
        float s = 0.f;
        for (int d = 0; d < EDIM; d++) {
            float u = 0.f;
            for (int c = 0; c < CC; c++)
                u += Wedge[(l * EDIM + d) * HC + h * CC + c] * attE[l * HC + h * CC + c];
            float ea;
            if (r < NRELS) {
                ea = eemb[r * EDIM + d];
            } else {
                float f = 0.f;
                for (int rr = 0; rr < NRELS; rr++)
                    f += (float)g_hist[rr] * eemb[rr * EDIM + d];
                ea = f / (float)EE;
            }
            s += ea * u;
        }
        g_serel[t] = s;
    }
    __syncthreads();
    if (t < 8) {                    // layer-0 rank-1 attention dots
        int h = t & 3;
        const float* av = (t < 4) ? attS : attD;
        float s = 0.f;
        for (int c = 0; c < CC; c++) s += g_w0sum[h * CC + c] * av[h * CC + c];
        g_k0[t] = s;
    }
}

// ---------- layer-0 aggregation: rank-1, direct-exp softmax ----------
__global__ void __launch_bounds__(256) k_agg0(const float* __restrict__ x,
                                              const float* __restrict__ bias,
                                              float* __restrict__ xout) {
    __shared__ float sser[(NRELS + 1) * HH];
    int t = threadIdx.x;
    if (t < (NRELS + 1) * HH) sser[t] = g_serel[t];
    __syncthreads();
    int warp = t >> 5, lane = t & 31;
    int n = blockIdx.x * 8 + warp;
    if (n >= NN) return;
    int hd = lane >> 3;
    float4 w4 = ((const float4*)g_w0sum)[lane];
    float k0s = g_k0[hd];
    int beg = g_rowstart[n], end = g_rowstart[n + 1];
    float sdv = x[n] * g_k0[4 + hd];
    float ds0 = 0.f, ds1 = 0.f, sx0 = 0.f, sx1 = 0.f;
    int cnt = end - beg;
    int npair = cnt >> 1;

    if (npair > 0) {
        unsigned pk0 = g_edgep[beg], pk1 = g_edgep[beg + 1];
        float xs0 = x[pk0 & 0xFFFFu], xs1 = x[pk1 & 0xFFFFu];
        for (int p = 0; p < npair; p++) {
            unsigned cp0 = pk0, cp1 = pk1;
            float cx0 = xs0, cx1 = xs1;
            int e2 = beg + 2 * (p + 1);
            if (p + 1 < npair) {
                pk0 = g_edgep[e2]; pk1 = g_edgep[e2 + 1];
                xs0 = x[pk0 & 0xFFFFu]; xs1 = x[pk1 & 0xFFFFu];
            }
            float a0 = cx0 * k0s + sdv + sser[(cp0 >> 16) * HH + hd];
            float a1 = cx1 * k0s + sdv + sser[(cp1 >> 16) * HH + hd];
            a0 = (a0 > 0.f) ? a0 : 0.2f * a0;
            a1 = (a1 > 0.f) ? a1 : 0.2f * a1;
            float w0 = __expf(a0), w1 = __expf(a1);
            ds0 += w0; sx0 += w0 * cx0;
            ds1 += w1; sx1 += w1 * cx1;
        }
    }
    if (cnt & 1) {
        unsigned p = g_edgep[end - 1];
        float xs = x[p & 0xFFFFu];
        float a = xs * k0s + sdv + sser[(p >> 16) * HH + hd];
        a = (a > 0.f) ? a : 0.2f * a;
        float w = __expf(a);
        ds0 += w; sx0 += w * xs;
    }
    float s = (sx0 + sx1) / (ds0 + ds1 + 1e-16f);
    float4 b4 = ((const float4*)bias)[lane];
    float4 o = make_float4(fmaxf(s * w4.x + b4.x, 0.f), fmaxf(s * w4.y + b4.y, 0.f),
                           fmaxf(s * w4.z + b4.z, 0.f), fmaxf(s * w4.w + b4.w, 0.f));
    ((float4*)xout)[n * 32 + lane] = o;
}

// ---------- layers 1,2 aggregation: warp per dst, 2-stream direct-exp ----------
__global__ void __launch_bounds__(256) k_agg(const float* __restrict__ bias,
                                             const float* __restrict__ xprev,
                                             float* __restrict__ xout, int layer) {
    __shared__ float sser[(NRELS + 1) * HH];
    int t = threadIdx.x;
    if (t < (NRELS + 1) * HH) sser[t] = g_serel[layer * (NRELS + 1) * HH + t];
    __syncthreads();
    int warp = t >> 5, lane = t & 31;
    int n = blockIdx.x * 8 + warp;
    if (n >= NN) return;
    int hd = lane >> 3;
    int beg = g_rowstart[n], end = g_rowstart[n + 1];
    float sdv = g_sdst[n * HH + hd];
    float ds0 = 0.f, ds1 = 0.f;
    float4 ac0 = make_float4(0.f, 0.f, 0.f, 0.f);
    float4 ac1 = make_float4(0.f, 0.f, 0.f, 0.f);
    int cnt = end - beg;
    int npair = cnt >> 1;

    if (npair > 0) {
        unsigned pk0 = g_edgep[beg], pk1 = g_edgep[beg + 1];
        int s0 = (int)(pk0 & 0xFFFFu), s1 = (int)(pk1 & 0xFFFFu);
        float ss0 = g_ssrc[s0 * HH + hd], ss1 = g_ssrc[s1 * HH + hd];
        uint2 rv0 = __ldg((const uint2*)(g_hh + s0 * HC) + lane);
        uint2 rv1 = __ldg((const uint2*)(g_hh + s1 * HC) + lane);
        for (int p = 0; p < npair; p++) {
            unsigned cp0 = pk0, cp1 = pk1;
            float cs0 = ss0, cs1 = ss1;
            uint2 cr0 = rv0, cr1 = rv1;
            int e2 = beg + 2 * (p + 1);
            if (p + 1 < npair) {
                pk0 = g_edgep[e2]; pk1 = g_edgep[e2 + 1];
                int t0 = (int)(pk0 & 0xFFFFu), t1 = (int)(pk1 & 0xFFFFu);
                ss0 = g_ssrc[t0 * HH + hd]; ss1 = g_ssrc[t1 * HH + hd];
                rv0 = __ldg((const uint2*)(g_hh + t0 * HC) + lane);
                rv1 = __ldg((const uint2*)(g_hh + t1 * HC) + lane);
            }
            float a0 = cs0 + sdv + sser[(cp0 >> 16) * HH + hd];
            float a1 = cs1 + sdv + sser[(cp1 >> 16) * HH + hd];
            a0 = (a0 > 0.f) ? a0 : 0.2f * a0;
            a1 = (a1 > 0.f) ? a1 : 0.2f * a1;
            float w0 = __expf(a0), w1 = __expf(a1);
            float2 f00 = __half22float2(*(const __half2*)&cr0.x);
            float2 f01 = __half22float2(*(const __half2*)&cr0.y);
            float2 f10 = __half22float2(*(const __half2*)&cr1.x);
            float2 f11 = __half22float2(*(const __half2*)&cr1.y);
            ds0 += w0;
            ac0.x += w0 * f00.x; ac0.y += w0 * f00.y;
            ac0.z += w0 * f01.x; ac0.w += w0 * f01.y;
            ds1 += w1;
            ac1.x += w1 * f10.x; ac1.y += w1 * f10.y;
            ac1.z += w1 * f11.x; ac1.w += w1 * f11.y;
        }
    }
    if (cnt & 1) {
        unsigned p = g_edgep[end - 1];
        int s = (int)(p & 0xFFFFu);
        float ss = g_ssrc[s * HH + hd];
        uint2 rv = __ldg((const uint2*)(g_hh + s * HC) + lane);
        float a = ss + sdv + sser[(p >> 16) * HH + hd];
        a = (a > 0.f) ? a : 0.2f * a;
        float w = __expf(a);
        float2 f0 = __half22float2(*(const __half2*)&rv.x);
        float2 f1 = __half22float2(*(const __half2*)&rv.y);
        ds0 += w;
        ac0.x += w * f0.x; ac0.y += w * f0.y;
        ac0.z += w * f1.x; ac0.w += w * f1.y;
    }
    float inv = 1.f / (ds0 + ds1 + 1e-16f);
    float4 b4 = ((const float4*)bias)[lane];
    float4 xp = ((const float4*)xprev)[n * 32 + lane];
    float4 o = make_float4((ac0.x + ac1.x) * inv + b4.x + xp.x,
                           (ac0.y + ac1.y) * inv + b4.y + xp.y,
                           (ac0.z + ac1.z) * inv + b4.z + xp.z,
                           (ac0.w + ac1.w) * inv + b4.w + xp.w);
    o.x = fmaxf(o.x, 0.f); o.y = fmaxf(o.y, 0.f);
    o.z = fmaxf(o.z, 0.f); o.w = fmaxf(o.w, 0.f);
    ((float4*)xout)[n * 32 + lane] = o;
}

// ---------- f32x2 SGEMM + fused epilogue: h(fp16), s_src, s_dst ----------
__global__ void __launch_bounds__(256) k_gemm(const float* __restrict__ A,
                                              const float* __restrict__ B,
                                              const float* __restrict__ attS,
                                              const float* __restrict__ attD,
                                              int M) {
    __shared__ float As[16][HC];
    __shared__ float Bs[16][HC];
    __shared__ float sa[HC], sd[HC];
    int t = threadIdx.x;
    int tx = t & 15, ty = t >> 4;
    int row0 = blockIdx.x * 128;
    if (t < HC) { sa[t] = attS[t]; sd[t] = attD[t]; }
    ull acc2[8][4];
#pragma unroll
    for (int i = 0; i < 8; i++)
#pragma unroll
        for (int j = 0; j < 4; j++) acc2[i][j] = 0ull;

    for (int kc = 0; kc < 128; kc += 16) {
#pragma unroll
        for (int i = 0; i < 2; i++) {
            int f = t * 2 + i;
            int r = f >> 2;
            int kq = (f & 3) << 2;
            float4 v = make_float4(0, 0, 0, 0);
            int gr = row0 + r;
            if (gr < M) v = *(const float4*)(A + gr * 128 + kc + kq);
            As[kq + 0][r] = v.x; As[kq + 1][r] = v.y;
            As[kq + 2][r] = v.z; As[kq + 3][r] = v.w;
        }
#pragma unroll
        for (int i = 0; i < 2; i++) {
            int f = t * 2 + i;
            int k = f >> 5;
            int cq = (f & 31) << 2;
            float4 v = *(const float4*)(B + (kc + k) * 128 + cq);
            Bs[k][cq + 0] = v.x; Bs[k][cq + 1] = v.y;
            Bs[k][cq + 2] = v.z; Bs[k][cq + 3] = v.w;
        }
        __syncthreads();
#pragma unroll
        for (int k = 0; k < 16; k++) {
            float4 a0 = *(const float4*)&As[k][ty * 8];
            float4 a1 = *(const float4*)&As[k][ty * 8 + 4];
            float4 b0 = *(const float4*)&Bs[k][tx * 8];
            float4 b1 = *(const float4*)&Bs[k][tx * 8 + 4];
            ull bb[4] = { pack2(b0.x, b0.y), pack2(b0.z, b0.w),
                          pack2(b1.x, b1.y), pack2(b1.z, b1.w) };
            float avs[8] = { a0.x, a0.y, a0.z, a0.w, a1.x, a1.y, a1.z, a1.w };
#pragma unroll
            for (int i = 0; i < 8; i++) {
                ull aa = pack2(avs[i], avs[i]);
#pragma unroll
                for (int j = 0; j < 4; j++) ffma2(acc2[i][j], aa, bb[j]);
            }
        }
        __syncthreads();
    }
    // epilogue: fp16 h store + fused s_src/s_dst (quad-shuffle over tx%4)
    int hd = tx >> 2;
#pragma unroll
    for (int i = 0; i < 8; i++) {
        int gr = row0 + ty * 8 + i;
        float f[8];
#pragma unroll
        for (int j = 0; j < 4; j++) { f[2 * j] = lo2(acc2[i][j]); f[2 * j + 1] = hi2(acc2[i][j]); }
        float ps = 0.f, pd = 0.f;
#pragma unroll
        for (int j = 0; j < 8; j++) {
            ps += f[j] * sa[tx * 8 + j];
            pd += f[j] * sd[tx * 8 + j];
        }
        ps += __shfl_xor_sync(0xffffffffu, ps, 1);
        pd += __shfl_xor_sync(0xffffffffu, pd, 1);
        ps += __shfl_xor_sync(0xffffffffu, ps, 2);
        pd += __shfl_xor_sync(0xffffffffu, pd, 2);
        if (gr < M) {
            __half2 h0 = __floats2half2_rn(f[0], f[1]);
            __half2 h1 = __floats2half2_rn(f[2], f[3]);
            __half2 h2 = __floats2half2_rn(f[4], f[5]);
            __half2 h3 = __floats2half2_rn(f[6], f[7]);
            uint4 u = make_uint4(*(unsigned*)&h0, *(unsigned*)&h1,
                                 *(unsigned*)&h2, *(unsigned*)&h3);
            *(uint4*)(g_hh + gr * HC + tx * 8) = u;
            if ((tx & 3) == 0) {
                g_ssrc[gr * HH + hd] = ps;
                g_sdst[gr * HH + hd] = pd;
            }
        }
    }
}

// ---------- fused MLP head: out = sigmoid(relu(A@W1+b1)@W2 + b2) ----------
__global__ void __launch_bounds__(256) k_mlp(const float* __restrict__ A,
                                             const float* __restrict__ W1,
                                             const float* __restrict__ b1,
                                             const float* __restrict__ W2,
                                             const float* __restrict__ b2,
                                             float* __restrict__ out, int M) {
    __shared__ float As[16][HC];
    __shared__ float Bs[16][HC];
    __shared__ float sred[128][17];
    __shared__ float sw2[HC];
    __shared__ float sb1[HC];
    int t = threadIdx.x;
    int tx = t & 15, ty = t >> 4;
    int row0 = blockIdx.x * 128;
    if (t < HC) {
        sw2[t] = (t < HID) ? W2[t] : 0.f;
        sb1[t] = (t < HID) ? b1[t] : 0.f;
    }
    ull acc2[8][4];
#pragma unroll
    for (int i = 0; i < 8; i++)
#pragma unroll
        for (int j = 0; j < 4; j++) acc2[i][j] = 0ull;

    for (int kc = 0; kc < 128; kc += 16) {
#pragma unroll
        for (int i = 0; i < 2; i++) {
            int f = t * 2 + i;
            int r = f >> 2;
            int kq = (f & 3) << 2;
            float4 v = make_float4(0, 0, 0, 0);
            int gr = row0 + r;
            if (gr < M) v = *(const float4*)(A + gr * 128 + kc + kq);
            As[kq + 0][r] = v.x; As[kq + 1][r] = v.y;
            As[kq + 2][r] = v.z; As[kq + 3][r] = v.w;
        }
#pragma unroll
        for (int i = 0; i < 2; i++) {
            int f = t * 2 + i;
            int k = f >> 5;
            int cq = (f & 31) << 2;
            float4 v = make_float4(0, 0, 0, 0);
            if (cq < HID) v = *(const float4*)(W1 + (kc + k) * HID + cq);
            Bs[k][cq + 0] = v.x; Bs[k][cq + 1] = v.y;
            Bs[k][cq + 2] = v.z; Bs[k][cq + 3] = v.w;
        }
        __syncthreads();
#pragma unroll
        for (int k = 0; k < 16; k++) {
            float4 a0 = *(const float4*)&As[k][ty * 8];
            float4 a1 = *(const float4*)&As[k][ty * 8 + 4];
            float4 b0 = *(const float4*)&Bs[k][tx * 8];
            float4 b1v = *(const float4*)&Bs[k][tx * 8 + 4];
            ull bb[4] = { pack2(b0.x, b0.y), pack2(b0.z, b0.w),
                          pack2(b1v.x, b1v.y), pack2(b1v.z, b1v.w) };
            float avs[8] = { a0.x, a0.y, a0.z, a0.w, a1.x, a1.y, a1.z, a1.w };
#pragma unroll
            for (int i = 0; i < 8; i++) {
                ull aa = pack2(avs[i], avs[i]);
#pragma unroll
                for (int j = 0; j < 4; j++) ffma2(acc2[i][j], aa, bb[j]);
            }
        }
        __syncthreads();
    }
#pragma unroll
    for (int i = 0; i < 8; i++) {
        float p = 0.f;
#pragma unroll
        for (int j = 0; j < 4; j++) {
            int gc = tx * 8 + 2 * j;
            float v0 = fmaxf(lo2(acc2[i][j]) + sb1[gc], 0.f);
            float v1 = fmaxf(hi2(acc2[i][j]) + sb1[gc + 1], 0.f);
            p += v0 * sw2[gc] + v1 * sw2[gc + 1];
        }
        sred[ty * 8 + i][tx] = p;
    }
    __syncthreads();
    if (t < 128) {
        int gr = row0 + t;
        if (gr < M) {
            float s = 0.f;
#pragma unroll
            for (int j = 0; j < 16; j++) s += sred[t][j];
            out[gr] = 1.f / (1.f + __expf(-(s + b2[0])));
        }
    }
}

// ---------- host ----------
extern "C" void kernel_launch(void* const* d_in, const int* in_sizes, int n_in,
                              void* d_out, int out_size) {
    const float* x     = (const float*)d_in[0];
    const int*   ei    = (const int*)d_in[1];
    const int*   et    = (const int*)d_in[2];
    const float* eemb  = (const float*)d_in[3];
    const float* W0    = (const float*)d_in[4];
    const float* W1    = (const float*)d_in[5];
    const float* W2    = (const float*)d_in[6];
    const float* attS  = (const float*)d_in[7];
    const float* attD  = (const float*)d_in[8];
    const float* attE  = (const float*)d_in[9];
    const float* Wedge = (const float*)d_in[10];
    const float* bias  = (const float*)d_in[11];
    const float* mW1   = (const float*)d_in[12];
    const float* mb1   = (const float*)d_in[13];
    const float* mW2   = (const float*)d_in[14];
    const float* mb2   = (const float*)d_in[15];
    float* out = (float*)d_out;

    float *pxA, *pxB;
    cudaGetSymbolAddress((void**)&pxA, g_xA);
    cudaGetSymbolAddress((void**)&pxB, g_xB);

    // graph build (reused by all 3 layers)
    k_init<<<(NN + 255) / 256, 256>>>();
    k_histcount<<<(EE + 255) / 256, 256>>>(ei, et);
    k_scan<<<1, 1024>>>();
    k_scatter<<<(EP + 255) / 256, 256>>>(ei, et);
    k_pre<<<1, 256>>>(W0, Wedge, attE, eemb, attS, attD);

    int gAgg = (NN + 7) / 8;
    int gGm  = (NN + 127) / 128;

    // layer 0: fully rank-1 aggregation (no h materialization at all)
    k_agg0<<<gAgg, 256>>>(x, bias + 0 * HC, pxA);

    // layer 1
    k_gemm<<<gGm, 256>>>(pxA, W1, attS + 1 * HC, attD + 1 * HC, NN);
    k_agg<<<gAgg, 256>>>(bias + 1 * HC, pxA, pxB, 1);

    // layer 2
    k_gemm<<<gGm, 256>>>(pxB, W2, attS + 2 * HC, attD + 2 * HC, NN);
    k_agg<<<gAgg, 256>>>(bias + 2 * HC, pxB, pxA, 2);

    // fused MLP head
    k_mlp<<<gGm, 256>>>(pxA, mW1, mb1, mW2, mb2, out, NN);
}